// round 4
// baseline (speedup 1.0000x reference)
#include <cuda_runtime.h>
#include <cub/cub.cuh>

#define NPTS 4096
#define FEAT 128
#define NEDGE (NPTS - 1)
#define NE 8386560                       // NPTS*(NPTS-1)/2
#define SEGPAD 8388608                   // 1<<23
#define PADCNT (SEGPAD - NE)
#define TOTKEYS 16777216
#define SENTK 0xFFFFFFFFFFFFFFFFULL
#define ECAP 4194304                     // candidate edge capacity per graph
#define CROUNDS 8
#define DROUNDS 5

// ---------------- static device scratch ----------------
__device__ float g_D[2][(size_t)NPTS * NPTS];
__device__ float g_sq[2][NPTS];
__device__ int g_capBits[2];
__device__ unsigned g_tau[2];
__device__ unsigned g_ncand[2];
__device__ unsigned g_edges[2 * NEDGE];
__device__ unsigned long long g_best[2][NPTS];
__device__ int g_comp[2][NPTS];
__device__ int g_ncomp[2];
__device__ int g_necnt[2];
__device__ unsigned long long g_elist[2][ECAP];     // (dbits<<24)|(a<<12)|b
__device__ __align__(256) unsigned g_keys[TOTKEYS];
__device__ __align__(256) unsigned g_keysAlt[TOTKEYS];
__device__ __align__(256) unsigned char g_temp[1u << 25];
__device__ float g_part[1024];

// ---------------- init ----------------
__global__ void init_kernel() {
    int t = blockIdx.x * blockDim.x + threadIdx.x;
    if (t < PADCNT) {
        g_keys[NE + t] = 0x7F7FFFFFu;
        g_keys[SEGPAD + NE + t] = 0xFFFFFFFFu;
    }
    if (t < NPTS) {
        g_comp[0][t] = t; g_comp[1][t] = t;
        g_best[0][t] = SENTK; g_best[1][t] = SENTK;
    }
    if (t == 0) {
        g_capBits[0] = 0; g_capBits[1] = 0;
        g_ncomp[0] = NPTS; g_ncomp[1] = NPTS;
        g_necnt[0] = 0; g_necnt[1] = 0;
        g_ncand[0] = 0; g_ncand[1] = 0;
    }
}

// ---------------- squared norms ----------------
__global__ void sqnorm_kernel(const float* __restrict__ X1, const float* __restrict__ X2) {
    int g = blockIdx.y;
    const float* __restrict__ X = g ? X2 : X1;
    int row = (blockIdx.x * blockDim.x + threadIdx.x) >> 5;
    int lane = threadIdx.x & 31;
    if (row >= NPTS) return;
    float s = 0.f;
#pragma unroll
    for (int c = lane; c < FEAT; c += 32) { float v = X[row * FEAT + c]; s += v * v; }
#pragma unroll
    for (int o = 16; o; o >>= 1) s += __shfl_down_sync(0xffffffffu, s, o);
    if (lane == 0) g_sq[g][row] = s;
}

// ---------------- distance matrix: 128x128 tiles, 8x8 micro (2x2 of 4x4) ----------------
__global__ void __launch_bounds__(256, 2) dist_kernel(const float* __restrict__ X1,
                                                      const float* __restrict__ X2) {
    int ti = blockIdx.y, tj = blockIdx.x;
    if (tj < ti) return;
    int g = blockIdx.z;
    const float* __restrict__ X = g ? X2 : X1;

    __shared__ __align__(16) float As[16][132];
    __shared__ __align__(16) float Bs[16][132];
    __shared__ float smax[256];

    int tx = threadIdx.x, ty = threadIdx.y;       // 16x16
    int tid = ty * 16 + tx;
    int i0 = ti * 128, j0 = tj * 128;

    float acc[2][2][4][4];
#pragma unroll
    for (int rh = 0; rh < 2; rh++)
#pragma unroll
        for (int ch = 0; ch < 2; ch++)
#pragma unroll
            for (int r = 0; r < 4; r++)
#pragma unroll
                for (int c = 0; c < 4; c++) acc[rh][ch][r][c] = 0.f;

    for (int k0 = 0; k0 < FEAT; k0 += 16) {
#pragma unroll
        for (int l = 0; l < 8; l++) {
            int lin = tid + l * 256;
            int m = lin >> 4, kk = lin & 15;
            As[kk][m] = X[(i0 + m) * FEAT + k0 + kk];
            Bs[kk][m] = X[(j0 + m) * FEAT + k0 + kk];
        }
        __syncthreads();
#pragma unroll
        for (int k = 0; k < 16; k++) {
            float4 a0 = *(const float4*)&As[k][ty * 4];
            float4 a1 = *(const float4*)&As[k][64 + ty * 4];
            float4 b0 = *(const float4*)&Bs[k][tx * 4];
            float4 b1 = *(const float4*)&Bs[k][64 + tx * 4];
            float av[2][4] = {{a0.x, a0.y, a0.z, a0.w}, {a1.x, a1.y, a1.z, a1.w}};
            float bv[2][4] = {{b0.x, b0.y, b0.z, b0.w}, {b1.x, b1.y, b1.z, b1.w}};
#pragma unroll
            for (int rh = 0; rh < 2; rh++)
#pragma unroll
                for (int ch = 0; ch < 2; ch++)
#pragma unroll
                    for (int r = 0; r < 4; r++)
#pragma unroll
                        for (int c = 0; c < 4; c++)
                            acc[rh][ch][r][c] += av[rh][r] * bv[ch][c];
        }
        __syncthreads();
    }

    float* Dg = g_D[g];
    float lmax = 0.f;
#pragma unroll
    for (int rh = 0; rh < 2; rh++) {
        float sqi[4], dval[2][4][4];
#pragma unroll
        for (int r = 0; r < 4; r++) sqi[r] = g_sq[g][i0 + rh * 64 + ty * 4 + r];
#pragma unroll
        for (int ch = 0; ch < 2; ch++) {
#pragma unroll
            for (int c = 0; c < 4; c++) {
                float sqj = g_sq[g][j0 + ch * 64 + tx * 4 + c];
#pragma unroll
                for (int r = 0; r < 4; r++) {
                    float d2 = sqi[r] + sqj - 2.f * acc[rh][ch][r][c];
                    d2 = fmaxf(d2, 0.f);
                    float d = (d2 > 1e-12f) ? sqrtf(d2) : 0.f;
                    dval[ch][r][c] = d;
                    lmax = fmaxf(lmax, d);
                }
            }
        }
#pragma unroll
        for (int r = 0; r < 4; r++) {
            size_t rowb = (size_t)(i0 + rh * 64 + ty * 4 + r) * NPTS + j0;
#pragma unroll
            for (int ch = 0; ch < 2; ch++)
                *(float4*)&Dg[rowb + ch * 64 + tx * 4] =
                    make_float4(dval[ch][r][0], dval[ch][r][1], dval[ch][r][2], dval[ch][r][3]);
        }
        if (ti != tj) {
#pragma unroll
            for (int ch = 0; ch < 2; ch++)
#pragma unroll
                for (int c = 0; c < 4; c++) {
                    size_t rowb = (size_t)(j0 + ch * 64 + tx * 4 + c) * NPTS + i0 + rh * 64;
                    *(float4*)&Dg[rowb + ty * 4] =
                        make_float4(dval[ch][0][c], dval[ch][1][c], dval[ch][2][c], dval[ch][3][c]);
                }
        }
    }
    smax[tid] = lmax;
    __syncthreads();
    for (int o = 128; o; o >>= 1) {
        if (tid < o) smax[tid] = fmaxf(smax[tid], smax[tid + o]);
        __syncthreads();
    }
    if (tid == 0) atomicMax(&g_capBits[g], __float_as_int(smax[0]));
}

// ---------------- tau: ~12.5% sample quantile (1 block/graph) ----------------
__global__ void __launch_bounds__(1024) sample_kernel() {
    int g = blockIdx.x;
    int t = threadIdx.x;
    __shared__ int hist[2048];
    __shared__ int sminB, smaxB, svalid;
    if (t == 0) { sminB = 0x7FFFFFFF; smaxB = 0; svalid = 0; }
    for (int i = t; i < 2048; i += 1024) hist[i] = 0;
    __syncthreads();
    const float* __restrict__ D = g_D[g];
    int lmin = 0x7FFFFFFF, lmax = 0, lval = 0;
    for (int s = 0; s < 64; s++) {
        unsigned idx = (((unsigned)(t * 64 + s)) * 2654435761u) & (unsigned)(NPTS * NPTS - 1);
        int db = __float_as_int(D[idx]);
        if (db > 0) { lmin = min(lmin, db); lmax = max(lmax, db); lval++; }
    }
    atomicMin(&sminB, lmin);
    atomicMax(&smaxB, lmax);
    atomicAdd(&svalid, lval);
    __syncthreads();
    unsigned minB = (unsigned)sminB;
    unsigned long long range = (unsigned long long)((unsigned)smaxB - minB) + 1;
    for (int s = 0; s < 64; s++) {
        unsigned idx = (((unsigned)(t * 64 + s)) * 2654435761u) & (unsigned)(NPTS * NPTS - 1);
        int db = __float_as_int(D[idx]);
        if (db > 0) {
            int b = (int)(((unsigned long long)((unsigned)db - minB) * 2048ull) / range);
            atomicAdd(&hist[min(b, 2047)], 1);
        }
    }
    __syncthreads();
    if (t == 0) {
        int target = svalid / 8;  // 12.5% -> avg degree ~512
        int acc = 0, bin = 2047;
        for (int i = 0; i < 2048; i++) {
            acc += hist[i];
            if (acc >= target) { bin = i; break; }
        }
        g_tau[g] = minB + (unsigned)(((unsigned long long)(bin + 1) * range) / 2048ull);
    }
}

// ---------------- persistence keys + fused candidate-edge compaction ----------------
__global__ void pfill_kernel() {
    int g = blockIdx.y;
    size_t idx = (size_t)blockIdx.x * blockDim.x + threadIdx.x;
    int i = (int)(idx >> 12);
    int j = (int)(idx & (NPTS - 1));
    bool up = (j > i);
    unsigned db = 0;
    if (up) {
        db = __float_as_uint(g_D[g][idx]);
        float cap = __int_as_float(g_capBits[g]);
        float per = cap - __uint_as_float(db);
        unsigned k = (unsigned)(((long long)i * (2 * NPTS - i - 1)) >> 1) + (unsigned)(j - i - 1);
        g_keys[(size_t)g * SEGPAD + k] = __float_as_uint(per) | (((unsigned)g) << 31);
    }
    bool w = up && (db < g_tau[g]);
    unsigned mask = __ballot_sync(0xffffffffu, w);
    if (w) {
        int lane = threadIdx.x & 31;
        int leader = __ffs(mask) - 1;
        int rank = __popc(mask & ((1u << lane) - 1));
        unsigned base = 0;
        if (lane == leader) base = atomicAdd(&g_ncand[g], (unsigned)__popc(mask));
        base = __shfl_sync(mask, base, leader);
        unsigned slot = base + rank;
        if (slot < ECAP)
            g_elist[g][slot] = ((unsigned long long)db << 24) | (unsigned)((i << 12) | j);
    }
}

// ---------------- Boruvka phase 1 (compact list) ----------------
__global__ void __launch_bounds__(256) cmin_kernel() {
    int g = blockIdx.y;
    if (g_ncomp[g] <= 1) return;
    unsigned E = g_ncand[g];
    if (E > ECAP) return;  // overflow: list unsafe, dense rounds take over
    __shared__ int scomp[NPTS];
    int t = threadIdx.x;
    for (int i = t; i < NPTS; i += 256) scomp[i] = g_comp[g][i];
    __syncthreads();
    const unsigned long long* __restrict__ el = g_elist[g];
    for (unsigned e = blockIdx.x * 256 + t; e < E; e += gridDim.x * 256) {
        unsigned long long k = el[e];
        unsigned eid = (unsigned)(k & 0xFFFFFFu);
        int cu = scomp[eid >> 12], cv = scomp[eid & 4095];
        if (cu != cv) {
            if (k < g_best[g][cu]) atomicMin(&g_best[g][cu], k);
            if (k < g_best[g][cv]) atomicMin(&g_best[g][cv], k);
        }
    }
}

// ---------------- Boruvka phase 1 (dense fallback/safety) ----------------
__global__ void __launch_bounds__(256) bmin_kernel() {
    int g = blockIdx.y;
    if (g_ncomp[g] <= 1) return;
    __shared__ int scomp[NPTS];
    int t = threadIdx.x;
    for (int i = t; i < NPTS; i += 256) scomp[i] = g_comp[g][i];
    __syncthreads();
    int warp = t >> 5, lane = t & 31;
    int r = blockIdx.x * 8 + warp;
    int myc = scomp[r];
    const float* __restrict__ row = g_D[g] + (size_t)r * NPTS;
    unsigned long long best = SENTK;
    for (int j0 = lane * 4; j0 < NPTS; j0 += 128) {
        float4 v = *(const float4*)(row + j0);
        float dv[4] = {v.x, v.y, v.z, v.w};
#pragma unroll
        for (int u = 0; u < 4; u++) {
            int j = j0 + u;
            if (scomp[j] != myc) {
                int a = min(r, j), b = max(r, j);
                unsigned long long k =
                    ((unsigned long long)__float_as_uint(dv[u]) << 24) |
                    (unsigned)((a << 12) | b);
                if (k < best) best = k;
            }
        }
    }
#pragma unroll
    for (int o = 16; o; o >>= 1) {
        unsigned long long ov = __shfl_down_sync(0xffffffffu, best, o);
        if (ov < best) best = ov;
    }
    if (lane == 0 && best != SENTK) atomicMin(&g_best[g][myc], best);
}

// ---------------- Boruvka phase 2: merge (1 block/graph) ----------------
__global__ void __launch_bounds__(1024) bmerge_kernel() {
    int g = blockIdx.x;
    if (g_ncomp[g] <= 1) return;
    __shared__ int par[NPTS];
    __shared__ int scnt;
    int t = threadIdx.x;
    for (int i = t; i < NPTS; i += 1024) par[i] = i;
    if (t == 0) scnt = 0;
    __syncthreads();
    for (int v = t; v < NPTS; v += 1024) {
        unsigned long long bk = g_best[g][v];
        if (bk != SENTK) {
            unsigned eid = (unsigned)(bk & 0xFFFFFFu);
            int a = (int)(eid >> 12), b = (int)(eid & 4095);
            int ca = g_comp[g][a], cb = g_comp[g][b];
            int other = (ca == v) ? cb : ca;
            bool add = !(g_best[g][other] == bk && other < v);
            if (add) {
                int slot = atomicAdd(&g_necnt[g], 1);
                if (slot < NEDGE) g_edges[g * NEDGE + slot] = eid;
            }
            par[v] = other;
        }
    }
    __syncthreads();
    for (int v = t; v < NPTS; v += 1024) {
        int p = par[v];
        if (p != v && par[p] == v && v < p) par[v] = v;
    }
    __syncthreads();
    for (int it = 0; it < 13; it++) {
        for (int v = t; v < NPTS; v += 1024) par[v] = par[par[v]];
        __syncthreads();
    }
    for (int i = t; i < NPTS; i += 1024) {
        g_comp[g][i] = par[g_comp[g][i]];
        g_best[g][i] = SENTK;
    }
    __syncthreads();
    int local = 0;
    for (int i = t; i < NPTS; i += 1024)
        if (g_comp[g][i] == i) local++;
    atomicAdd(&scnt, local);
    __syncthreads();
    if (t == 0) g_ncomp[g] = scnt;
}

// ---------------- zero-out tree edges ----------------
__global__ void fixup_kernel() {
    int e = blockIdx.x * blockDim.x + threadIdx.x;
    if (e >= 2 * NEDGE) return;
    int g = e / NEDGE;
    int i = e % NEDGE;
    unsigned pk = g_edges[g * NEDGE + i];
    int u = (int)(pk >> 12), v = (int)(pk & 4095);
    int a = u < v ? u : v;
    int b = u < v ? v : u;
    unsigned k = (unsigned)(((long long)a * (2 * NPTS - a - 1)) >> 1) + (unsigned)(b - a - 1);
    g_keys[(size_t)g * SEGPAD + k] = ((unsigned)g) << 31;
}

// ---------------- Wasserstein sum ----------------
__global__ void wsum1_kernel(const unsigned* __restrict__ keys) {
    __shared__ float sh[256];
    float s = 0.f;
    for (size_t k = (size_t)blockIdx.x * blockDim.x + threadIdx.x; k < NE;
         k += (size_t)gridDim.x * blockDim.x) {
        float a = __uint_as_float(keys[k]);
        float b = __uint_as_float(keys[SEGPAD + k] & 0x7FFFFFFFu);
        s += fabsf(a - b);
    }
    sh[threadIdx.x] = s;
    __syncthreads();
    for (int o = 128; o; o >>= 1) {
        if (threadIdx.x < o) sh[threadIdx.x] += sh[threadIdx.x + o];
        __syncthreads();
    }
    if (threadIdx.x == 0) g_part[blockIdx.x] = sh[0];
}

__global__ void wsum2_kernel(float* __restrict__ out) {
    __shared__ double sh[1024];
    sh[threadIdx.x] = (double)g_part[threadIdx.x];
    __syncthreads();
    for (int o = 512; o; o >>= 1) {
        if (threadIdx.x < o) sh[threadIdx.x] += sh[threadIdx.x + o];
        __syncthreads();
    }
    if (threadIdx.x == 0) out[0] = (float)sh[0];
}

// ---------------- launch ----------------
extern "C" void kernel_launch(void* const* d_in, const int* in_sizes, int n_in,
                              void* d_out, int out_size) {
    const float* X1 = (const float*)d_in[0];
    const float* X2 = (const float*)d_in[2];
    float* out = (float*)d_out;

    init_kernel<<<16, 256>>>();
    sqnorm_kernel<<<dim3(NPTS / 8, 2), 256>>>(X1, X2);
    dist_kernel<<<dim3(32, 32, 2), dim3(16, 16)>>>(X1, X2);
    sample_kernel<<<2, 1024>>>();
    pfill_kernel<<<dim3((NPTS * NPTS) / 256, 2), 256>>>();

    for (int r = 0; r < CROUNDS; r++) {
        cmin_kernel<<<dim3(256, 2), 256>>>();
        bmerge_kernel<<<2, 1024>>>();
    }
    for (int r = 0; r < DROUNDS; r++) {
        bmin_kernel<<<dim3(NPTS / 8, 2), 256>>>();
        bmerge_kernel<<<2, 1024>>>();
    }

    fixup_kernel<<<(2 * NEDGE + 255) / 256, 256>>>();

    unsigned *keys, *alt;
    void* tempp;
    cudaGetSymbolAddress((void**)&keys, g_keys);
    cudaGetSymbolAddress((void**)&alt, g_keysAlt);
    cudaGetSymbolAddress(&tempp, g_temp);

    cub::DoubleBuffer<unsigned> db(keys, alt);
    size_t bytes = 0;
    cub::DeviceRadixSort::SortKeys(nullptr, bytes, db, TOTKEYS, 0, 32, (cudaStream_t)0);
    cub::DeviceRadixSort::SortKeys(tempp, bytes, db, TOTKEYS, 0, 32, (cudaStream_t)0);

    const unsigned* sorted = db.Current();
    wsum1_kernel<<<1024, 256>>>(sorted);
    wsum2_kernel<<<1, 1024>>>(out);
}